// round 8
// baseline (speedup 1.0000x reference)
#include <cuda_runtime.h>
#include <cuda_bf16.h>
#include <cstdint>

#define HDIM 2048
#define NEXP 64
#define TOPK 8
#define BK   32
#define NIT  (HDIM / BK)     // 64
#define APAD 36              // floats per A row (9 granules, odd -> conflict-free)

typedef unsigned long long ull;

// d.lo = fma(a.lo,b.lo,d.lo); d.hi = fma(a.hi,b.hi,d.hi). Each 32-bit lane is an
// exact sequential fp32 FMA chain (matches reference accumulation rounding).
__device__ __forceinline__ void ffma2(ull &d, ull a, ull b) {
    asm("fma.rn.f32x2 %0, %1, %2, %0;" : "+l"(d) : "l"(a), "l"(b));
}
__device__ __forceinline__ ull splat2(float x) {
    ull r; asm("mov.b64 %0, {%1, %1};" : "=l"(r) : "f"(x)); return r;
}
__device__ __forceinline__ void cpa16(uint32_t s, const void* g) {
    asm volatile("cp.async.cg.shared.global [%0], [%1], 16;" :: "r"(s), "l"(g));
}
__device__ __forceinline__ void cpa_commit() {
    asm volatile("cp.async.commit_group;");
}
template <int N>
__device__ __forceinline__ void cpa_wait() {
    asm volatile("cp.async.wait_group %0;" :: "n"(N));
}
__device__ __forceinline__ uint32_t s2u(const void* p) {
    return (uint32_t)__cvta_generic_to_shared(p);
}

// k-major copy of gate_w: gwT[k][e]
__device__ float g_gwT[HDIM * NEXP];

__global__ void transpose_gw(const float* __restrict__ gw) {
    __shared__ float t[32][33];
    int k0 = blockIdx.x * 32, e0 = blockIdx.y * 32;
#pragma unroll
    for (int r = 0; r < 32; r += 8)
        t[threadIdx.y + r][threadIdx.x] =
            gw[(size_t)(e0 + threadIdx.y + r) * HDIM + k0 + threadIdx.x];
    __syncthreads();
#pragma unroll
    for (int r = 0; r < 32; r += 8)
        g_gwT[(size_t)(k0 + threadIdx.y + r) * NEXP + e0 + threadIdx.x] =
            t[threadIdx.x][threadIdx.y + r];
}

struct Smem {
    union {
        float A[2][64][APAD];        // 18432 B  (double-buffered A tiles)
        float logits[64][65];        // 16640 B  (aliases A after GEMM)
    };
    float B[2][BK][NEXP];            // 16384 B  (k-major B tiles)
    float bias[NEXP];
};
static_assert(sizeof(Smem) < 36 * 1024, "smem budget");

__global__ __launch_bounds__(256)
void router_kernel(const float* __restrict__ hs,
                   const float* __restrict__ bias,
                   float* __restrict__ out, int T)
{
    __shared__ Smem sm;
    const int tid = threadIdx.x;
    const int tx  = tid & 15;        // experts 4tx..4tx+3
    const int ty  = tid >> 4;        // tokens  4ty..4ty+3  (ty 0..15)
    const int t0  = blockIdx.x * 64;

    if (tid < NEXP) sm.bias[tid] = bias[tid];

    // fill tile 'buf' with k-range [kk, kk+32)
    auto fill = [&](int buf, int kk) {
        // A: 64 rows x 8 real granules = 512 granules; row = idx>>3, kc = idx&7.
        // 8 lanes cover one row's 128 B contiguously -> fully coalesced.
#pragma unroll
        for (int m = 0; m < 2; m++) {
            int idx = tid + 256 * m;
            int row = idx >> 3, kc = idx & 7;
            cpa16(s2u(&sm.A[buf][row][kc * 4]),
                  &hs[(size_t)(t0 + row) * HDIM + kk + kc * 4]);
        }
        // B: 32 k x 16 granules = 512 granules (gwT tile is 8 KB contiguous)
#pragma unroll
        for (int m = 0; m < 2; m++) {
            int idx = tid + 256 * m;
            int k = idx >> 4, eg = idx & 15;
            cpa16(s2u(&sm.B[buf][k][eg * 4]),
                  &g_gwT[(size_t)(kk + k) * NEXP + eg * 4]);
        }
        cpa_commit();
    };

    // acc[i][p]: token 4ty+i, expert pair (4tx+2p, 4tx+2p+1)
    ull acc[4][2];
#pragma unroll
    for (int i = 0; i < 4; i++) { acc[i][0] = 0ull; acc[i][1] = 0ull; }

    fill(0, 0);

    for (int it = 0; it < NIT; it++) {
        if (it + 1 < NIT) { fill((it + 1) & 1, (it + 1) * BK); cpa_wait<1>(); }
        else              { cpa_wait<0>(); }
        __syncthreads();

        const int s = it & 1;
#pragma unroll
        for (int kq = 0; kq < BK / 4; kq++) {       // 4 k's per step
            float4 a[4];
#pragma unroll
            for (int i = 0; i < 4; i++)
                a[i] = *reinterpret_cast<const float4*>(
                    &sm.A[s][4 * ty + i][kq * 4]);
#pragma unroll
            for (int d = 0; d < 4; d++) {           // ascending k
                float4 b = *reinterpret_cast<const float4*>(
                    &sm.B[s][kq * 4 + d][4 * tx]);
                ull b0 = *reinterpret_cast<ull*>(&b.x);
                ull b1 = *reinterpret_cast<ull*>(&b.z);
#pragma unroll
                for (int i = 0; i < 4; i++) {
                    const float av = (d == 0) ? a[i].x : (d == 1) ? a[i].y
                                   : (d == 2) ? a[i].z : a[i].w;
                    ull as = splat2(av);
                    ffma2(acc[i][0], as, b0);
                    ffma2(acc[i][1], as, b1);
                }
            }
        }
        __syncthreads();   // all reads of buf done before next fill overwrites it
    }

    // store logits (aliases A -> already synced above)
#pragma unroll
    for (int i = 0; i < 4; i++)
#pragma unroll
        for (int p = 0; p < 2; p++) {
            float2 v = *reinterpret_cast<float2*>(&acc[i][p]);
            sm.logits[4 * ty + i][4 * tx + 2 * p]     = v.x;
            sm.logits[4 * ty + i][4 * tx + 2 * p + 1] = v.y;
        }
    __syncthreads();

    // ---- fused epilogue: 1 thread per token ----
    if (tid < 64) {
        const int t = t0 + tid;
        float* L = sm.logits[tid];

        float mx = -3.4e38f;
#pragma unroll
        for (int e = 0; e < NEXP; e++) mx = fmaxf(mx, L[e]);
        float ssum = 0.f;
        for (int e = 0; e < NEXP; e++) {
            float ex = expf(L[e] - mx);
            L[e] = ex;
            ssum += ex;
        }
        const float inv = 1.f / ssum;

        // top-8 on score + bias; strict '>' == stable tie-break (lower idx wins)
        float tv[8]; int ti[8];
#pragma unroll
        for (int k = 0; k < 8; k++) { tv[k] = -3.4e38f; ti[k] = 0; }
        for (int e = 0; e < NEXP; e++) {
            float v = L[e] * inv + sm.bias[e];
            int idx = e;
#pragma unroll
            for (int k = 0; k < 8; k++) {
                if (v > tv[k]) {
                    float fv = tv[k]; int fi = ti[k];
                    tv[k] = v; ti[k] = idx;
                    v = fv;  idx = fi;
                }
            }
        }

        float pv[8]; float ps = 0.f;
#pragma unroll
        for (int k = 0; k < 8; k++) { pv[k] = L[ti[k]] * inv; ps += pv[k]; }
        const float rn = 1.f / (ps + 1e-9f);

        float* __restrict__ probs = out;
        float* __restrict__ idxo  = out + (size_t)T * 8;
        float* __restrict__ rmap  = out + (size_t)T * 16;
#pragma unroll
        for (int k = 0; k < 8; k++) {
            probs[(size_t)t * 8 + k] = pv[k] * rn;
            idxo [(size_t)t * 8 + k] = (float)ti[k];
        }
        ull mask = 0;
#pragma unroll
        for (int k = 0; k < 8; k++) mask |= (1ull << ti[k]);
        float4* rp = reinterpret_cast<float4*>(&rmap[(size_t)t * 64]);
#pragma unroll
        for (int g = 0; g < 16; g++) {
            float4 vv;
            vv.x = ((mask >> (g * 4 + 0)) & 1ull) ? 1.f : 0.f;
            vv.y = ((mask >> (g * 4 + 1)) & 1ull) ? 1.f : 0.f;
            vv.z = ((mask >> (g * 4 + 2)) & 1ull) ? 1.f : 0.f;
            vv.w = ((mask >> (g * 4 + 3)) & 1ull) ? 1.f : 0.f;
            rp[g] = vv;
        }
    }

    if (blockIdx.x == 0 && tid == 0)
        out[(size_t)T * 80] = 0.f;   // aux_loss
}

extern "C" void kernel_launch(void* const* d_in, const int* in_sizes, int n_in,
                              void* d_out, int out_size)
{
    const float* hs   = (const float*)d_in[0];  // [T, 2048]
    const float* gw   = (const float*)d_in[1];  // [64, 2048]
    const float* bias = (const float*)d_in[2];  // [64]
    const int T = in_sizes[0] / HDIM;

    dim3 tg(32, 8);
    dim3 tb(HDIM / 32, NEXP / 32);
    transpose_gw<<<tb, tg>>>(gw);
    router_kernel<<<(T + 63) / 64, 256>>>(hs, bias, (float*)d_out, T);
}

// round 9
// speedup vs baseline: 1.0997x; 1.0997x over previous
#include <cuda_runtime.h>
#include <cuda_bf16.h>
#include <cstdint>

#define HDIM 2048
#define NEXP 64
#define TOPK 8
#define BK   64
#define NIT  (HDIM / BK)     // 32
#define APAD 68              // floats per A row: 17 granules (16 data + 1 pad)

typedef unsigned long long ull;

// d.lo = fma(a.lo,b.lo,d.lo); d.hi = fma(a.hi,b.hi,d.hi). Each 32-bit lane is an
// exact sequential fp32 FMA chain (matches reference accumulation rounding).
__device__ __forceinline__ void ffma2(ull &d, ull a, ull b) {
    asm("fma.rn.f32x2 %0, %1, %2, %0;" : "+l"(d) : "l"(a), "l"(b));
}
__device__ __forceinline__ ull splat2(float x) {
    ull r; asm("mov.b64 %0, {%1, %1};" : "=l"(r) : "f"(x)); return r;
}
__device__ __forceinline__ void cpa16(uint32_t s, const void* g) {
    asm volatile("cp.async.cg.shared.global [%0], [%1], 16;" :: "r"(s), "l"(g));
}
__device__ __forceinline__ void cpa_commit() {
    asm volatile("cp.async.commit_group;");
}
template <int N>
__device__ __forceinline__ void cpa_wait() {
    asm volatile("cp.async.wait_group %0;" :: "n"(N));
}
__device__ __forceinline__ uint32_t s2u(const void* p) {
    return (uint32_t)__cvta_generic_to_shared(p);
}

// k-major copy of gate_w: gwT[k][e]
__device__ float g_gwT[HDIM * NEXP];

__global__ void transpose_gw(const float* __restrict__ gw) {
    __shared__ float t[32][33];
    int k0 = blockIdx.x * 32, e0 = blockIdx.y * 32;
#pragma unroll
    for (int r = 0; r < 32; r += 8)
        t[threadIdx.y + r][threadIdx.x] =
            gw[(size_t)(e0 + threadIdx.y + r) * HDIM + k0 + threadIdx.x];
    __syncthreads();
#pragma unroll
    for (int r = 0; r < 32; r += 8)
        g_gwT[(size_t)(k0 + threadIdx.y + r) * NEXP + e0 + threadIdx.x] =
            t[threadIdx.x][threadIdx.y + r];
}

struct Smem {
    union {
        float A[2][64][APAD];        // 34816 B (double-buffered, col-swizzled)
        float logits[64][65];        // 16640 B (aliases A after GEMM)
    };
    float B[2][BK][NEXP];            // 32768 B
    float bias[NEXP];
};
// 67840 B -> dynamic smem

__global__ __launch_bounds__(128)
void router_kernel(const float* __restrict__ hs,
                   const float* __restrict__ bias,
                   float* __restrict__ out, int T)
{
    extern __shared__ char smem_raw[];
    Smem& sm = *reinterpret_cast<Smem*>(smem_raw);
    const int tid = threadIdx.x;
    const int tx  = tid & 15;        // experts 4tx..4tx+3
    const int ty  = tid >> 4;        // tokens  8ty..8ty+7  (ty 0..7)
    const int t0  = blockIdx.x * 64;

    if (tid < NEXP) sm.bias[tid] = bias[tid];

    // fill tile 'buf' with k-range [kk, kk+64).
    // A column swizzle: data granule kc of row stored at granule kc ^ (row>>3).
    // Reads at (kq ^ ty) then hit distinct banks for the warp's two rows.
    auto fill = [&](int buf, int kk) {
#pragma unroll
        for (int m = 0; m < 8; m++) {                 // A: 64 rows x 16 granules
            int idx = tid + 128 * m;
            int row = idx >> 4, kc = idx & 15;
            int skc = kc ^ ((row >> 3) & 7);
            cpa16(s2u(&sm.A[buf][row][skc * 4]),
                  &hs[(size_t)(t0 + row) * HDIM + kk + kc * 4]);
        }
#pragma unroll
        for (int m = 0; m < 8; m++) {                 // B: 64 k x 16 granules
            int idx = tid + 128 * m;
            int k = idx >> 4, eg = idx & 15;
            cpa16(s2u(&sm.B[buf][k][eg * 4]),
                  &g_gwT[(size_t)(kk + k) * NEXP + eg * 4]);
        }
        cpa_commit();
    };

    // acc[i][p]: token 8ty+i, expert pair (4tx+2p, 4tx+2p+1)
    ull acc[8][2];
#pragma unroll
    for (int i = 0; i < 8; i++) { acc[i][0] = 0ull; acc[i][1] = 0ull; }

    fill(0, 0);

    for (int it = 0; it < NIT; it++) {
        if (it + 1 < NIT) { fill((it + 1) & 1, (it + 1) * BK); cpa_wait<1>(); }
        else              { cpa_wait<0>(); }
        __syncthreads();

        const int s = it & 1;
#pragma unroll
        for (int kq = 0; kq < BK / 4; kq++) {       // 4 k's per step
            const int akq = (kq ^ ty) * 4;          // de-swizzle (row>>3 == ty)
            float4 a[8];
#pragma unroll
            for (int i = 0; i < 8; i++)
                a[i] = *reinterpret_cast<const float4*>(
                    &sm.A[s][8 * ty + i][akq]);
#pragma unroll
            for (int d = 0; d < 4; d++) {           // ascending k
                float4 b = *reinterpret_cast<const float4*>(
                    &sm.B[s][kq * 4 + d][4 * tx]);
                ull b0 = *reinterpret_cast<ull*>(&b.x);
                ull b1 = *reinterpret_cast<ull*>(&b.z);
#pragma unroll
                for (int i = 0; i < 8; i++) {
                    const float av = (d == 0) ? a[i].x : (d == 1) ? a[i].y
                                   : (d == 2) ? a[i].z : a[i].w;
                    ull as = splat2(av);
                    ffma2(acc[i][0], as, b0);
                    ffma2(acc[i][1], as, b1);
                }
            }
        }
        __syncthreads();   // all reads of buf done before next fill overwrites it
    }

    // store logits (aliases A -> already synced above)
#pragma unroll
    for (int i = 0; i < 8; i++)
#pragma unroll
        for (int p = 0; p < 2; p++) {
            float2 v = *reinterpret_cast<float2*>(&acc[i][p]);
            sm.logits[8 * ty + i][4 * tx + 2 * p]     = v.x;
            sm.logits[8 * ty + i][4 * tx + 2 * p + 1] = v.y;
        }
    __syncthreads();

    // ---- fused epilogue: 1 thread per token ----
    if (tid < 64) {
        const int t = t0 + tid;
        float* L = sm.logits[tid];

        float mx = -3.4e38f;
#pragma unroll
        for (int e = 0; e < NEXP; e++) mx = fmaxf(mx, L[e]);
        float ssum = 0.f;
        for (int e = 0; e < NEXP; e++) {
            float ex = expf(L[e] - mx);
            L[e] = ex;
            ssum += ex;
        }
        const float inv = 1.f / ssum;

        // top-8 on score + bias; strict '>' == stable tie-break (lower idx wins)
        float tv[8]; int ti[8];
#pragma unroll
        for (int k = 0; k < 8; k++) { tv[k] = -3.4e38f; ti[k] = 0; }
        for (int e = 0; e < NEXP; e++) {
            float v = L[e] * inv + sm.bias[e];
            int idx = e;
#pragma unroll
            for (int k = 0; k < 8; k++) {
                if (v > tv[k]) {
                    float fv = tv[k]; int fi = ti[k];
                    tv[k] = v; ti[k] = idx;
                    v = fv;  idx = fi;
                }
            }
        }

        float pv[8]; float ps = 0.f;
#pragma unroll
        for (int k = 0; k < 8; k++) { pv[k] = L[ti[k]] * inv; ps += pv[k]; }
        const float rn = 1.f / (ps + 1e-9f);

        float* __restrict__ probs = out;
        float* __restrict__ idxo  = out + (size_t)T * 8;
        float* __restrict__ rmap  = out + (size_t)T * 16;
#pragma unroll
        for (int k = 0; k < 8; k++) {
            probs[(size_t)t * 8 + k] = pv[k] * rn;
            idxo [(size_t)t * 8 + k] = (float)ti[k];
        }
        ull mask = 0;
#pragma unroll
        for (int k = 0; k < 8; k++) mask |= (1ull << ti[k]);
        float4* rp = reinterpret_cast<float4*>(&rmap[(size_t)t * 64]);
#pragma unroll
        for (int g = 0; g < 16; g++) {
            float4 vv;
            vv.x = ((mask >> (g * 4 + 0)) & 1ull) ? 1.f : 0.f;
            vv.y = ((mask >> (g * 4 + 1)) & 1ull) ? 1.f : 0.f;
            vv.z = ((mask >> (g * 4 + 2)) & 1ull) ? 1.f : 0.f;
            vv.w = ((mask >> (g * 4 + 3)) & 1ull) ? 1.f : 0.f;
            rp[g] = vv;
        }
    }

    if (blockIdx.x == 0 && tid == 0)
        out[(size_t)T * 80] = 0.f;   // aux_loss
}

extern "C" void kernel_launch(void* const* d_in, const int* in_sizes, int n_in,
                              void* d_out, int out_size)
{
    const float* hs   = (const float*)d_in[0];  // [T, 2048]
    const float* gw   = (const float*)d_in[1];  // [64, 2048]
    const float* bias = (const float*)d_in[2];  // [64]
    const int T = in_sizes[0] / HDIM;

    cudaFuncSetAttribute(router_kernel,
                         cudaFuncAttributeMaxDynamicSharedMemorySize,
                         (int)sizeof(Smem));

    dim3 tg(32, 8);
    dim3 tb(HDIM / 32, NEXP / 32);
    transpose_gw<<<tb, tg>>>(gw);
    router_kernel<<<(T + 63) / 64, 128, sizeof(Smem)>>>(hs, bias, (float*)d_out, T);
}

// round 10
// speedup vs baseline: 1.1009x; 1.0010x over previous
#include <cuda_runtime.h>
#include <cuda_bf16.h>
#include <cstdint>

#define HDIM 2048
#define NEXP 64
#define TOPK 8
#define BK   64
#define NIT  (HDIM / BK)     // 32
#define APAD 68              // floats per A row: 17 granules (16 data + 1 pad)

typedef unsigned long long ull;

// d.lo = fma(a.lo,b.lo,d.lo); d.hi = fma(a.hi,b.hi,d.hi). Each 32-bit lane is an
// exact sequential fp32 FMA chain (matches reference accumulation rounding).
__device__ __forceinline__ void ffma2(ull &d, ull a, ull b) {
    asm("fma.rn.f32x2 %0, %1, %2, %0;" : "+l"(d) : "l"(a), "l"(b));
}
__device__ __forceinline__ ull splat2(float x) {
    ull r; asm("mov.b64 %0, {%1, %1};" : "=l"(r) : "f"(x)); return r;
}
__device__ __forceinline__ void cpa16(uint32_t s, const void* g) {
    asm volatile("cp.async.cg.shared.global [%0], [%1], 16;" :: "r"(s), "l"(g));
}
__device__ __forceinline__ void cpa_commit() {
    asm volatile("cp.async.commit_group;");
}
template <int N>
__device__ __forceinline__ void cpa_wait() {
    asm volatile("cp.async.wait_group %0;" :: "n"(N));
}
__device__ __forceinline__ uint32_t s2u(const void* p) {
    return (uint32_t)__cvta_generic_to_shared(p);
}

// k-major copy of gate_w: gwT[k][e]
__device__ float g_gwT[HDIM * NEXP];

__global__ void transpose_gw(const float* __restrict__ gw) {
    __shared__ float t[32][33];
    int k0 = blockIdx.x * 32, e0 = blockIdx.y * 32;
#pragma unroll
    for (int r = 0; r < 32; r += 8)
        t[threadIdx.y + r][threadIdx.x] =
            gw[(size_t)(e0 + threadIdx.y + r) * HDIM + k0 + threadIdx.x];
    __syncthreads();
#pragma unroll
    for (int r = 0; r < 32; r += 8)
        g_gwT[(size_t)(k0 + threadIdx.y + r) * NEXP + e0 + threadIdx.x] =
            t[threadIdx.x][threadIdx.y + r];
}

struct Smem {
    union {
        float A[2][64][APAD];        // 34816 B (double-buffered, col-swizzled)
        float logits[64][65];        // 16640 B (aliases A after GEMM)
    };
    float B[2][BK][NEXP];            // 32768 B
    float bias[NEXP];
};
// 67840 B -> dynamic smem

__global__ __launch_bounds__(128)
void router_kernel(const float* __restrict__ hs,
                   const float* __restrict__ bias,
                   float* __restrict__ out, int T)
{
    extern __shared__ char smem_raw[];
    Smem& sm = *reinterpret_cast<Smem*>(smem_raw);
    const int tid = threadIdx.x;
    const int tx  = tid & 15;        // experts 4tx..4tx+3
    const int ty  = tid >> 4;        // tokens  8ty..8ty+7  (ty 0..7)
    const int t0  = blockIdx.x * 64;

    if (tid < NEXP) sm.bias[tid] = bias[tid];

    // fill tile 'buf' with k-range [kk, kk+64).
    // A column swizzle: data granule kc of row stored at granule kc ^ (row>>3).
    auto fill = [&](int buf, int kk) {
#pragma unroll
        for (int m = 0; m < 8; m++) {                 // A: 64 rows x 16 granules
            int idx = tid + 128 * m;
            int row = idx >> 4, kc = idx & 15;
            int skc = kc ^ ((row >> 3) & 7);
            cpa16(s2u(&sm.A[buf][row][skc * 4]),
                  &hs[(size_t)(t0 + row) * HDIM + kk + kc * 4]);
        }
#pragma unroll
        for (int m = 0; m < 8; m++) {                 // B: 64 k x 16 granules
            int idx = tid + 128 * m;
            int k = idx >> 4, eg = idx & 15;
            cpa16(s2u(&sm.B[buf][k][eg * 4]),
                  &g_gwT[(size_t)(kk + k) * NEXP + eg * 4]);
        }
        cpa_commit();
    };

    // acc[i][p]: token 8ty+i, expert pair (4tx+2p, 4tx+2p+1)
    ull acc[8][2];
#pragma unroll
    for (int i = 0; i < 8; i++) { acc[i][0] = 0ull; acc[i][1] = 0ull; }

    fill(0, 0);

    for (int it = 0; it < NIT; it++) {
        if (it + 1 < NIT) { fill((it + 1) & 1, (it + 1) * BK); cpa_wait<1>(); }
        else              { cpa_wait<0>(); }
        __syncthreads();

        const int s = it & 1;
#pragma unroll
        for (int kq = 0; kq < BK / 4; kq++) {       // 4 k's per step
            const int akq = (kq ^ ty) * 4;          // de-swizzle (row>>3 == ty)
            // ---- batched load phase: 12 LDS.128 back-to-back, no consumers ----
            float4 a[8];
#pragma unroll
            for (int i = 0; i < 8; i++)
                a[i] = *reinterpret_cast<const float4*>(
                    &sm.A[s][8 * ty + i][akq]);
            float4 bq[4];
#pragma unroll
            for (int d = 0; d < 4; d++)
                bq[d] = *reinterpret_cast<const float4*>(
                    &sm.B[s][kq * 4 + d][4 * tx]);
            // ---- pure compute phase: splats + FFMA2, no memory deps ----
#pragma unroll
            for (int d = 0; d < 4; d++) {           // ascending k
                ull b0 = *reinterpret_cast<ull*>(&bq[d].x);
                ull b1 = *reinterpret_cast<ull*>(&bq[d].z);
#pragma unroll
                for (int i = 0; i < 8; i++) {
                    const float av = (d == 0) ? a[i].x : (d == 1) ? a[i].y
                                   : (d == 2) ? a[i].z : a[i].w;
                    ull as = splat2(av);
                    ffma2(acc[i][0], as, b0);
                    ffma2(acc[i][1], as, b1);
                }
            }
        }
        __syncthreads();   // all reads of buf done before next fill overwrites it
    }

    // store logits (aliases A -> already synced above)
#pragma unroll
    for (int i = 0; i < 8; i++)
#pragma unroll
        for (int p = 0; p < 2; p++) {
            float2 v = *reinterpret_cast<float2*>(&acc[i][p]);
            sm.logits[8 * ty + i][4 * tx + 2 * p]     = v.x;
            sm.logits[8 * ty + i][4 * tx + 2 * p + 1] = v.y;
        }
    __syncthreads();

    // ---- fused epilogue: 1 thread per token ----
    if (tid < 64) {
        const int t = t0 + tid;
        float* L = sm.logits[tid];

        float mx = -3.4e38f;
#pragma unroll
        for (int e = 0; e < NEXP; e++) mx = fmaxf(mx, L[e]);
        float ssum = 0.f;
        for (int e = 0; e < NEXP; e++) {
            float ex = expf(L[e] - mx);
            L[e] = ex;
            ssum += ex;
        }
        const float inv = 1.f / ssum;

        // top-8 on score + bias; strict '>' == stable tie-break (lower idx wins)
        float tv[8]; int ti[8];
#pragma unroll
        for (int k = 0; k < 8; k++) { tv[k] = -3.4e38f; ti[k] = 0; }
        for (int e = 0; e < NEXP; e++) {
            float v = L[e] * inv + sm.bias[e];
            int idx = e;
#pragma unroll
            for (int k = 0; k < 8; k++) {
                if (v > tv[k]) {
                    float fv = tv[k]; int fi = ti[k];
                    tv[k] = v; ti[k] = idx;
                    v = fv;  idx = fi;
                }
            }
        }

        float pv[8]; float ps = 0.f;
#pragma unroll
        for (int k = 0; k < 8; k++) { pv[k] = L[ti[k]] * inv; ps += pv[k]; }
        const float rn = 1.f / (ps + 1e-9f);

        float* __restrict__ probs = out;
        float* __restrict__ idxo  = out + (size_t)T * 8;
        float* __restrict__ rmap  = out + (size_t)T * 16;
#pragma unroll
        for (int k = 0; k < 8; k++) {
            probs[(size_t)t * 8 + k] = pv[k] * rn;
            idxo [(size_t)t * 8 + k] = (float)ti[k];
        }
        ull mask = 0;
#pragma unroll
        for (int k = 0; k < 8; k++) mask |= (1ull << ti[k]);
        float4* rp = reinterpret_cast<float4*>(&rmap[(size_t)t * 64]);
#pragma unroll
        for (int g = 0; g < 16; g++) {
            float4 vv;
            vv.x = ((mask >> (g * 4 + 0)) & 1ull) ? 1.f : 0.f;
            vv.y = ((mask >> (g * 4 + 1)) & 1ull) ? 1.f : 0.f;
            vv.z = ((mask >> (g * 4 + 2)) & 1ull) ? 1.f : 0.f;
            vv.w = ((mask >> (g * 4 + 3)) & 1ull) ? 1.f : 0.f;
            rp[g] = vv;
        }
    }

    if (blockIdx.x == 0 && tid == 0)
        out[(size_t)T * 80] = 0.f;   // aux_loss
}

extern "C" void kernel_launch(void* const* d_in, const int* in_sizes, int n_in,
                              void* d_out, int out_size)
{
    const float* hs   = (const float*)d_in[0];  // [T, 2048]
    const float* gw   = (const float*)d_in[1];  // [64, 2048]
    const float* bias = (const float*)d_in[2];  // [64]
    const int T = in_sizes[0] / HDIM;

    cudaFuncSetAttribute(router_kernel,
                         cudaFuncAttributeMaxDynamicSharedMemorySize,
                         (int)sizeof(Smem));

    dim3 tg(32, 8);
    dim3 tb(HDIM / 32, NEXP / 32);
    transpose_gw<<<tb, tg>>>(gw);
    router_kernel<<<(T + 63) / 64, 128, sizeof(Smem)>>>(hs, bias, (float*)d_out, T);
}

// round 11
// speedup vs baseline: 1.1137x; 1.0116x over previous
#include <cuda_runtime.h>
#include <cuda_bf16.h>
#include <cstdint>

#define HDIM 2048
#define NEXP 64
#define TOPK 8
#define BK   64
#define NIT  (HDIM / BK)     // 32
#define APAD 68              // floats per A row: 17 granules (16 data + 1 pad)
#define TILE_T 56            // tokens per CTA -> 293 CTAs <= 296 resident slots

typedef unsigned long long ull;

// d.lo = fma(a.lo,b.lo,d.lo); d.hi = fma(a.hi,b.hi,d.hi). Each 32-bit lane is an
// exact sequential fp32 FMA chain (matches reference accumulation rounding).
__device__ __forceinline__ void ffma2(ull &d, ull a, ull b) {
    asm("fma.rn.f32x2 %0, %1, %2, %0;" : "+l"(d) : "l"(a), "l"(b));
}
__device__ __forceinline__ ull splat2(float x) {
    ull r; asm("mov.b64 %0, {%1, %1};" : "=l"(r) : "f"(x)); return r;
}
__device__ __forceinline__ void cpa16(uint32_t s, const void* g) {
    asm volatile("cp.async.cg.shared.global [%0], [%1], 16;" :: "r"(s), "l"(g));
}
__device__ __forceinline__ void cpa_commit() {
    asm volatile("cp.async.commit_group;");
}
template <int N>
__device__ __forceinline__ void cpa_wait() {
    asm volatile("cp.async.wait_group %0;" :: "n"(N));
}
__device__ __forceinline__ uint32_t s2u(const void* p) {
    return (uint32_t)__cvta_generic_to_shared(p);
}

// k-major copy of gate_w: gwT[k][e]
__device__ float g_gwT[HDIM * NEXP];

__global__ void transpose_gw(const float* __restrict__ gw) {
    __shared__ float t[32][33];
    int k0 = blockIdx.x * 32, e0 = blockIdx.y * 32;
#pragma unroll
    for (int r = 0; r < 32; r += 8)
        t[threadIdx.y + r][threadIdx.x] =
            gw[(size_t)(e0 + threadIdx.y + r) * HDIM + k0 + threadIdx.x];
    __syncthreads();
#pragma unroll
    for (int r = 0; r < 32; r += 8)
        g_gwT[(size_t)(k0 + threadIdx.y + r) * NEXP + e0 + threadIdx.x] =
            t[threadIdx.x][threadIdx.y + r];
}

struct Smem {
    union {
        float A[2][64][APAD];        // 34816 B (double-buffered, col-swizzled)
        float logits[64][65];        // 16640 B (aliases A after GEMM)
    };
    float B[2][BK][NEXP];            // 32768 B
    float bias[NEXP];
};
// 67840 B -> dynamic smem (2 CTAs/SM fit in 228 KB carveout)

__global__ __launch_bounds__(128)
void router_kernel(const float* __restrict__ hs,
                   const float* __restrict__ bias,
                   float* __restrict__ out, int T)
{
    extern __shared__ char smem_raw[];
    Smem& sm = *reinterpret_cast<Smem*>(smem_raw);
    const int tid = threadIdx.x;
    const int tx  = tid & 15;        // experts 4tx..4tx+3
    const int ty  = tid >> 4;        // tokens  8ty..8ty+7  (ty 0..7; ty==7 redundant)
    const int t0  = blockIdx.x * TILE_T;

    if (tid < NEXP) sm.bias[tid] = bias[tid];

    // fill tile 'buf' with k-range [kk, kk+64).
    // A column swizzle: data granule kc of row stored at granule kc ^ (row>>3).
    // Token row clamped to T-1 (rows >= TILE_T / beyond T are dummies, discarded).
    auto fill = [&](int buf, int kk) {
#pragma unroll
        for (int m = 0; m < 8; m++) {                 // A: 64 rows x 16 granules
            int idx = tid + 128 * m;
            int row = idx >> 4, kc = idx & 15;
            int skc = kc ^ ((row >> 3) & 7);
            int trow = t0 + row; if (trow > T - 1) trow = T - 1;
            cpa16(s2u(&sm.A[buf][row][skc * 4]),
                  &hs[(size_t)trow * HDIM + kk + kc * 4]);
        }
#pragma unroll
        for (int m = 0; m < 8; m++) {                 // B: 64 k x 16 granules
            int idx = tid + 128 * m;
            int k = idx >> 4, eg = idx & 15;
            cpa16(s2u(&sm.B[buf][k][eg * 4]),
                  &g_gwT[(size_t)(kk + k) * NEXP + eg * 4]);
        }
        cpa_commit();
    };

    // acc[i][p]: token 8ty+i, expert pair (4tx+2p, 4tx+2p+1)
    ull acc[8][2];
#pragma unroll
    for (int i = 0; i < 8; i++) { acc[i][0] = 0ull; acc[i][1] = 0ull; }

    fill(0, 0);

    for (int it = 0; it < NIT; it++) {
        if (it + 1 < NIT) { fill((it + 1) & 1, (it + 1) * BK); cpa_wait<1>(); }
        else              { cpa_wait<0>(); }
        __syncthreads();

        const int s = it & 1;
#pragma unroll
        for (int kq = 0; kq < BK / 4; kq++) {       // 4 k's per step
            const int akq = (kq ^ ty) * 4;          // de-swizzle (row>>3 == ty)
            float4 a[8];
#pragma unroll
            for (int i = 0; i < 8; i++)
                a[i] = *reinterpret_cast<const float4*>(
                    &sm.A[s][8 * ty + i][akq]);
            float4 bq[4];
#pragma unroll
            for (int d = 0; d < 4; d++)
                bq[d] = *reinterpret_cast<const float4*>(
                    &sm.B[s][kq * 4 + d][4 * tx]);
#pragma unroll
            for (int d = 0; d < 4; d++) {           // ascending k
                ull b0 = *reinterpret_cast<ull*>(&bq[d].x);
                ull b1 = *reinterpret_cast<ull*>(&bq[d].z);
#pragma unroll
                for (int i = 0; i < 8; i++) {
                    const float av = (d == 0) ? a[i].x : (d == 1) ? a[i].y
                                   : (d == 2) ? a[i].z : a[i].w;
                    ull as = splat2(av);
                    ffma2(acc[i][0], as, b0);
                    ffma2(acc[i][1], as, b1);
                }
            }
        }
        __syncthreads();   // all reads of buf done before next fill overwrites it
    }

    // store logits (aliases A -> already synced above)
#pragma unroll
    for (int i = 0; i < 8; i++)
#pragma unroll
        for (int p = 0; p < 2; p++) {
            float2 v = *reinterpret_cast<float2*>(&acc[i][p]);
            sm.logits[8 * ty + i][4 * tx + 2 * p]     = v.x;
            sm.logits[8 * ty + i][4 * tx + 2 * p + 1] = v.y;
        }
    __syncthreads();

    // ---- fused epilogue: 1 thread per real token ----
    if (tid < TILE_T && t0 + tid < T) {
        const int t = t0 + tid;
        float* L = sm.logits[tid];

        float mx = -3.4e38f;
#pragma unroll
        for (int e = 0; e < NEXP; e++) mx = fmaxf(mx, L[e]);
        float ssum = 0.f;
        for (int e = 0; e < NEXP; e++) {
            float ex = expf(L[e] - mx);
            L[e] = ex;
            ssum += ex;
        }
        const float inv = 1.f / ssum;

        // top-8 on score + bias; strict '>' == stable tie-break (lower idx wins)
        float tv[8]; int ti[8];
#pragma unroll
        for (int k = 0; k < 8; k++) { tv[k] = -3.4e38f; ti[k] = 0; }
        for (int e = 0; e < NEXP; e++) {
            float v = L[e] * inv + sm.bias[e];
            int idx = e;
#pragma unroll
            for (int k = 0; k < 8; k++) {
                if (v > tv[k]) {
                    float fv = tv[k]; int fi = ti[k];
                    tv[k] = v; ti[k] = idx;
                    v = fv;  idx = fi;
                }
            }
        }

        float pv[8]; float ps = 0.f;
#pragma unroll
        for (int k = 0; k < 8; k++) { pv[k] = L[ti[k]] * inv; ps += pv[k]; }
        const float rn = 1.f / (ps + 1e-9f);

        float* __restrict__ probs = out;
        float* __restrict__ idxo  = out + (size_t)T * 8;
        float* __restrict__ rmap  = out + (size_t)T * 16;
#pragma unroll
        for (int k = 0; k < 8; k++) {
            probs[(size_t)t * 8 + k] = pv[k] * rn;
            idxo [(size_t)t * 8 + k] = (float)ti[k];
        }
        ull mask = 0;
#pragma unroll
        for (int k = 0; k < 8; k++) mask |= (1ull << ti[k]);
        float4* rp = reinterpret_cast<float4*>(&rmap[(size_t)t * 64]);
#pragma unroll
        for (int g = 0; g < 16; g++) {
            float4 vv;
            vv.x = ((mask >> (g * 4 + 0)) & 1ull) ? 1.f : 0.f;
            vv.y = ((mask >> (g * 4 + 1)) & 1ull) ? 1.f : 0.f;
            vv.z = ((mask >> (g * 4 + 2)) & 1ull) ? 1.f : 0.f;
            vv.w = ((mask >> (g * 4 + 3)) & 1ull) ? 1.f : 0.f;
            rp[g] = vv;
        }
    }

    if (blockIdx.x == 0 && tid == 0)
        out[(size_t)T * 80] = 0.f;   // aux_loss
}

extern "C" void kernel_launch(void* const* d_in, const int* in_sizes, int n_in,
                              void* d_out, int out_size)
{
    const float* hs   = (const float*)d_in[0];  // [T, 2048]
    const float* gw   = (const float*)d_in[1];  // [64, 2048]
    const float* bias = (const float*)d_in[2];  // [64]
    const int T = in_sizes[0] / HDIM;

    cudaFuncSetAttribute(router_kernel,
                         cudaFuncAttributeMaxDynamicSharedMemorySize,
                         (int)sizeof(Smem));

    dim3 tg(32, 8);
    dim3 tb(HDIM / 32, NEXP / 32);
    transpose_gw<<<tb, tg>>>(gw);
    router_kernel<<<(T + TILE_T - 1) / TILE_T, 128, sizeof(Smem)>>>(
        hs, bias, (float*)d_out, T);
}